// round 8
// baseline (speedup 1.0000x reference)
#include <cuda_runtime.h>
#include <cuda_bf16.h>
#include <math.h>
#include <stdint.h>

// ---------------------------------------------------------------------------
// ChildSumTreeLSTM via HMMA (mma.sync bf16), fp32 accuracy via 3-term split
// computed with register-level fragment reuse:
//   load Ah,Al,Bh,Bl fragments once per k-chunk; acc += Ah*Bh + Al*Bh + Ah*Bl
// K = 256 physical (no K-expansion) -> 33% less LDSM traffic per MMA.
// ---------------------------------------------------------------------------

#define N_NODES   87381
#define N_INT     21845
#define LEAF_OFF  21845
#define N_LEAVES  65536
#define KDIM      256
#define NKCH      8            // 256/32

// generic 128x128 core smem layout (per stage)
#define G_AL      10240
#define G_BH      20480
#define G_BL      30720
#define GSTAGE    40960
#define SPITCH    132
#define BIG_SMEM  (2 * GSTAGE)           // 81920 (>= SPITCH*128*4 = 67584)

// leaf 128x96 core smem layout (per stage)
#define L_AL      10240
#define L_BH      20480
#define L_BL      28160
#define LSTAGE    35840
#define LPITCH    100
#define LEAF_SMEM (3 * LSTAGE)           // 107520 (>= 128*LPITCH*4 = 51200)

// --------------------------- device scratch --------------------------------
__device__ __align__(256) float         g_XW[(size_t)N_INT * 1024];     // 4j+g
__device__ __align__(256) float         g_c [(size_t)N_NODES * 256];
__device__ __align__(256) __nv_bfloat16 g_x_hi[(size_t)N_NODES * 256];
__device__ __align__(256) __nv_bfloat16 g_x_lo[(size_t)N_NODES * 256];
__device__ __align__(256) __nv_bfloat16 g_h_hi[(size_t)N_NODES * 256];
__device__ __align__(256) __nv_bfloat16 g_h_lo[(size_t)N_NODES * 256];
__device__ __align__(256) __nv_bfloat16 g_hs_hi[16384 * 256];
__device__ __align__(256) __nv_bfloat16 g_hs_lo[16384 * 256];
__device__ __align__(256) float         g_iouh[(size_t)16384 * 768];    // 3j+g
__device__ __align__(256) float         g_fh  [(size_t)65536 * 256];
__device__ __align__(256) __nv_bfloat16 g_Wcat_hi[1024 * 256];          // 4j+g
__device__ __align__(256) __nv_bfloat16 g_Wcat_lo[1024 * 256];
__device__ __align__(256) __nv_bfloat16 g_Wiou_hi[768 * 256];           // 3j+g
__device__ __align__(256) __nv_bfloat16 g_Wiou_lo[768 * 256];
__device__ __align__(256) __nv_bfloat16 g_Wiouh_hi[768 * 256];          // 3j+g
__device__ __align__(256) __nv_bfloat16 g_Wiouh_lo[768 * 256];
__device__ __align__(256) __nv_bfloat16 g_Wfh_hi[256 * 256];
__device__ __align__(256) __nv_bfloat16 g_Wfh_lo[256 * 256];
__device__ float g_bcat[1024];                                          // 4j+g
__device__ float g_b3[768];                                             // 3j+g
__device__ float g_hroot[256];

// --------------------------- helpers ---------------------------------------
__device__ __forceinline__ float fsig(float v) {
    return __fdividef(1.0f, 1.0f + __expf(-v));
}
__device__ __forceinline__ float ftanh(float v) {
    float a = fabsf(v);
    float e = __expf(-2.0f * a);
    float t = __fdividef(1.0f - e, 1.0f + e);
    return copysignf(t, v);
}
__device__ __forceinline__ void split2(float v, __nv_bfloat16* hi, __nv_bfloat16* lo) {
    __nv_bfloat16 h = __float2bfloat16(v);
    *hi = h;
    *lo = __float2bfloat16(v - __bfloat162float(h));
}
__device__ __forceinline__ uint32_t smem_u32(const void* p) {
    uint32_t a;
    asm("{ .reg .u64 t; cvta.to.shared.u64 t, %1; cvt.u32.u64 %0, t; }" : "=r"(a) : "l"(p));
    return a;
}
__device__ __forceinline__ void cp_async16(uint32_t dst, const void* src, int sz) {
    asm volatile("cp.async.ca.shared.global [%0], [%1], 16, %2;"
                 :: "r"(dst), "l"(src), "r"(sz) : "memory");
}
__device__ __forceinline__ void ldmatrix_x4(uint32_t* r, uint32_t addr) {
    asm volatile("ldmatrix.sync.aligned.m8n8.x4.shared.b16 {%0,%1,%2,%3}, [%4];"
                 : "=r"(r[0]), "=r"(r[1]), "=r"(r[2]), "=r"(r[3]) : "r"(addr));
}
__device__ __forceinline__ void mma16816(float* c, const uint32_t* a, const uint32_t* b) {
    asm volatile(
        "mma.sync.aligned.m16n8k16.row.col.f32.bf16.bf16.f32 "
        "{%0,%1,%2,%3}, {%4,%5,%6,%7}, {%8,%9}, {%0,%1,%2,%3};"
        : "+f"(c[0]), "+f"(c[1]), "+f"(c[2]), "+f"(c[3])
        : "r"(a[0]), "r"(a[1]), "r"(a[2]), "r"(a[3]), "r"(b[0]), "r"(b[1]));
}

// --------------------------- pack kernels ----------------------------------
__global__ void split_x(const float* __restrict__ x) {
    const size_t idx = (size_t)blockIdx.x * 256 + threadIdx.x;
    split2(x[idx], &g_x_hi[idx], &g_x_lo[idx]);
}

// Wcat rows p = 4j+g (internal x-GEMM)
__global__ void pack_wcat(const float* __restrict__ Wix, const float* __restrict__ bix,
                          const float* __restrict__ bih,
                          const float* __restrict__ Wfx, const float* __restrict__ bfx,
                          const float* __restrict__ bfh) {
    const int p = blockIdx.x;
    const int jj = threadIdx.x;
    const int j = p >> 2, g = p & 3;
    float v = (g < 3) ? Wix[(g * 256 + j) * 256 + jj] : Wfx[j * 256 + jj];
    split2(v, &g_Wcat_hi[p * 256 + jj], &g_Wcat_lo[p * 256 + jj]);
    if (jj == 0)
        g_bcat[p] = (g < 3) ? (bix[g * 256 + j] + bih[g * 256 + j]) : (bfx[j] + bfh[j]);
}

// Merged: Wiou (leaf GEMM, 3j+g), Wiouh (3j+g), Wfh
__global__ void pack_rest(const float* __restrict__ Wix, const float* __restrict__ bix,
                          const float* __restrict__ bih,
                          const float* __restrict__ Wiouh, const float* __restrict__ Wfh) {
    const int b = blockIdx.x;           // 0..1791
    const int jj = threadIdx.x;
    if (b < 768) {
        const int j = b / 3, g = b % 3;
        split2(Wix[(g * 256 + j) * 256 + jj], &g_Wiou_hi[b * 256 + jj], &g_Wiou_lo[b * 256 + jj]);
        if (jj == 0) g_b3[b] = bix[g * 256 + j] + bih[g * 256 + j];
    } else if (b < 1536) {
        const int p = b - 768;
        const int j = p / 3, g = p % 3;
        split2(Wiouh[(g * 256 + j) * 256 + jj], &g_Wiouh_hi[p * 256 + jj], &g_Wiouh_lo[p * 256 + jj]);
    } else {
        const int r = b - 1536;
        split2(Wfh[r * 256 + jj], &g_Wfh_hi[r * 256 + jj], &g_Wfh_lo[r * 256 + jj]);
    }
}

// --------------------------- leaf GEMM (128x96, 3-stage, occ2) -------------
// acc = Ah*Bh + Al*Bh + Ah*Bl over K=256. Fused leaf activation epilogue.
__global__ __launch_bounds__(256, 2)
void gemm_leaf(const __nv_bfloat16* __restrict__ Ah_, const __nv_bfloat16* __restrict__ Al_,
               const __nv_bfloat16* __restrict__ Bh_, const __nv_bfloat16* __restrict__ Bl_) {
    extern __shared__ __align__(16) char smd[];
    const int tid  = threadIdx.x;
    const int wid  = tid >> 5;
    const int lane = tid & 31;
    const int bm = blockIdx.y * 128;
    const int bn = blockIdx.x * 96;
    const int wm = (wid >> 1) * 32;
    const int wn = (wid & 1) * 48;
    const uint32_t sb = smem_u32(smd);

    float acc[2][6][4];
#pragma unroll
    for (int i = 0; i < 2; i++)
#pragma unroll
        for (int n = 0; n < 6; n++)
#pragma unroll
            for (int q = 0; q < 4; q++) acc[i][n][q] = 0.0f;

#define LLOAD(c, st) do {                                                          \
        const int k0 = (c) * 32;                                                   \
        uint32_t bs = sb + (st) * LSTAGE;                                          \
        _Pragma("unroll")                                                          \
        for (int s = 0; s < 7; s++) {                                              \
            int id = tid + s * 256;                                                \
            if (id < 512) {                                                        \
                int r = id >> 2, q = id & 3;                                       \
                cp_async16(bs + r * 80 + q * 16,                                   \
                           Ah_ + (size_t)(bm + r) * KDIM + k0 + q * 8, 16);        \
            } else if (id < 1024) {                                                \
                int o = id - 512; int r = o >> 2, q = o & 3;                       \
                cp_async16(bs + L_AL + r * 80 + q * 16,                            \
                           Al_ + (size_t)(bm + r) * KDIM + k0 + q * 8, 16);        \
            } else if (id < 1408) {                                                \
                int o = id - 1024; int r = o >> 2, q = o & 3;                      \
                cp_async16(bs + L_BH + r * 80 + q * 16,                            \
                           Bh_ + (size_t)(bn + r) * KDIM + k0 + q * 8, 16);        \
            } else {                                                               \
                int o = id - 1408; int r = o >> 2, q = o & 3;                      \
                cp_async16(bs + L_BL + r * 80 + q * 16,                            \
                           Bl_ + (size_t)(bn + r) * KDIM + k0 + q * 8, 16);        \
            }                                                                      \
        }                                                                          \
        asm volatile("cp.async.commit_group;" ::: "memory");                       \
    } while (0)

    LLOAD(0, 0);
    LLOAD(1, 1);
    const uint32_t lrow = lane & 15;
    const uint32_t lcol = (lane >> 4) * 16;

    for (int c = 0; c < NKCH; c++) {
        const int st = c % 3;
        if (c + 2 < NKCH) {
            LLOAD(c + 2, (c + 2) % 3);
            asm volatile("cp.async.wait_group 2;" ::: "memory");
        } else if (c + 1 < NKCH) {
            asm volatile("cp.async.wait_group 1;" ::: "memory");
        } else {
            asm volatile("cp.async.wait_group 0;" ::: "memory");
        }
        __syncthreads();

        const uint32_t a_h = sb + st * LSTAGE + (wm + lrow) * 80 + lcol;
        const uint32_t b_h = sb + st * LSTAGE + L_BH + (wn + lrow) * 80 + lcol;
#pragma unroll
        for (int ks = 0; ks < 2; ks++) {
            const uint32_t ko = ks * 32;
            uint32_t ah[2][4], bh[6][2];
            ldmatrix_x4(ah[0], a_h + ko);
            ldmatrix_x4(ah[1], a_h + 16 * 80 + ko);
#pragma unroll
            for (int j = 0; j < 3; j++) {
                uint32_t r[4];
                ldmatrix_x4(r, b_h + j * 16 * 80 + ko);
                bh[2 * j][0] = r[0]; bh[2 * j][1] = r[2];
                bh[2 * j + 1][0] = r[1]; bh[2 * j + 1][1] = r[3];
            }
#pragma unroll
            for (int i = 0; i < 2; i++)
#pragma unroll
                for (int n = 0; n < 6; n++)
                    mma16816(acc[i][n], ah[i], bh[n]);
            // Al * Bh (Bh dies after this group)
            {
                uint32_t al[2][4];
                ldmatrix_x4(al[0], a_h + (L_AL) + ko);
                ldmatrix_x4(al[1], a_h + (L_AL) + 16 * 80 + ko);
#pragma unroll
                for (int i = 0; i < 2; i++)
#pragma unroll
                    for (int n = 0; n < 6; n++)
                        mma16816(acc[i][n], al[i], bh[n]);
            }
            // Ah * Bl
            {
                uint32_t bl[6][2];
#pragma unroll
                for (int j = 0; j < 3; j++) {
                    uint32_t r[4];
                    ldmatrix_x4(r, b_h + (L_BL - L_BH) + j * 16 * 80 + ko);
                    bl[2 * j][0] = r[0]; bl[2 * j][1] = r[2];
                    bl[2 * j + 1][0] = r[1]; bl[2 * j + 1][1] = r[3];
                }
#pragma unroll
                for (int i = 0; i < 2; i++)
#pragma unroll
                    for (int n = 0; n < 6; n++)
                        mma16816(acc[i][n], ah[i], bl[n]);
            }
        }
        __syncthreads();
    }
#undef LLOAD

    // ---- stage tile to smem (aliases pipeline buffers) ----
    float* Cs = (float*)smd;
#pragma unroll
    for (int i = 0; i < 2; i++) {
        const int r = wm + i * 16 + (lane >> 2);
#pragma unroll
        for (int n = 0; n < 6; n++) {
            const int col = wn + n * 8 + (lane & 3) * 2;
            *(float2*)(Cs + r * LPITCH + col) = make_float2(acc[i][n][0], acc[i][n][1]);
            *(float2*)(Cs + (r + 8) * LPITCH + col) = make_float2(acc[i][n][2], acc[i][n][3]);
        }
    }
    __syncthreads();

    // ---- leaf activation: 128 rows x 32 features, 2 features per thread ----
    const int j0 = 32 * blockIdx.x;
#pragma unroll 2
    for (int it = 0; it < 8; it++) {
        const int idx = it * 256 + tid;
        const int r = idx >> 4;
        const int t = 2 * (idx & 15);
        const float* cr = Cs + r * LPITCH + 3 * t;
        const float* bb = g_b3 + bn + 3 * t;
        float i0 = fsig (cr[0] + bb[0]);
        float o0 = fsig (cr[1] + bb[1]);
        float u0 = ftanh(cr[2] + bb[2]);
        float c0 = i0 * u0;
        float h0 = o0 * ftanh(c0);
        float i1 = fsig (cr[3] + bb[3]);
        float o1 = fsig (cr[4] + bb[4]);
        float u1 = ftanh(cr[5] + bb[5]);
        float c1 = i1 * u1;
        float h1 = o1 * ftanh(c1);

        const size_t node = (size_t)LEAF_OFF + bm + r;
        const int j = j0 + t;
        *(float2*)(g_c + node * 256 + j) = make_float2(c0, c1);

        __nv_bfloat16 hh0 = __float2bfloat16(h0);
        __nv_bfloat16 hh1 = __float2bfloat16(h1);
        __nv_bfloat162 hw = {hh0, hh1};
        __nv_bfloat162 lw = __floats2bfloat162_rn(h0 - __bfloat162float(hh0),
                                                  h1 - __bfloat162float(hh1));
        *(uint32_t*)(g_h_hi + node * 256 + j) = *reinterpret_cast<uint32_t*>(&hw);
        *(uint32_t*)(g_h_lo + node * 256 + j) = *reinterpret_cast<uint32_t*>(&lw);
    }
}

// --------------------------- generic 128x128 mainloop ----------------------
__device__ __forceinline__ void mainloop128(
    const __nv_bfloat16* __restrict__ Ah_, const __nv_bfloat16* __restrict__ Al_,
    const __nv_bfloat16* __restrict__ Bh_, const __nv_bfloat16* __restrict__ Bl_,
    int M, int bm, int bn, uint32_t sb, int tid, int wid, int lane,
    float (&acc)[2][8][4])
{
    const int wm = (wid >> 1) * 32;
    const int wn = (wid & 1) * 64;

#define GLOAD(c, st) do {                                                          \
        const int k0 = (c) * 32;                                                   \
        uint32_t bs = sb + (st) * GSTAGE;                                          \
        _Pragma("unroll")                                                          \
        for (int s = 0; s < 8; s++) {                                              \
            int id = tid + s * 256;                                                \
            int seg = id >> 9;                                                     \
            int o = id & 511;                                                      \
            int r = o >> 2, q = o & 3;                                             \
            if (seg == 0)                                                          \
                cp_async16(bs + r * 80 + q * 16,                                   \
                           Ah_ + (size_t)(bm + r) * KDIM + k0 + q * 8,             \
                           (bm + r < M) ? 16 : 0);                                 \
            else if (seg == 1)                                                     \
                cp_async16(bs + G_AL + r * 80 + q * 16,                            \
                           Al_ + (size_t)(bm + r) * KDIM + k0 + q * 8,             \
                           (bm + r < M) ? 16 : 0);                                 \
            else if (seg == 2)                                                     \
                cp_async16(bs + G_BH + r * 80 + q * 16,                            \
                           Bh_ + (size_t)(bn + r) * KDIM + k0 + q * 8, 16);        \
            else                                                                   \
                cp_async16(bs + G_BL + r * 80 + q * 16,                            \
                           Bl_ + (size_t)(bn + r) * KDIM + k0 + q * 8, 16);        \
        }                                                                          \
        asm volatile("cp.async.commit_group;" ::: "memory");                       \
    } while (0)

    GLOAD(0, 0);
    const uint32_t lrow = lane & 15;
    const uint32_t lcol = (lane >> 4) * 16;

    for (int c = 0; c < NKCH; c++) {
        const int st = c & 1;
        if (c + 1 < NKCH) {
            GLOAD(c + 1, st ^ 1);
            asm volatile("cp.async.wait_group 1;" ::: "memory");
        } else {
            asm volatile("cp.async.wait_group 0;" ::: "memory");
        }
        __syncthreads();

        const uint32_t a_h = sb + st * GSTAGE + (wm + lrow) * 80 + lcol;
        const uint32_t b_h = sb + st * GSTAGE + G_BH + (wn + lrow) * 80 + lcol;
#pragma unroll
        for (int ks = 0; ks < 2; ks++) {
            const uint32_t ko = ks * 32;
            uint32_t ah[2][4], bh[8][2];
            ldmatrix_x4(ah[0], a_h + ko);
            ldmatrix_x4(ah[1], a_h + 16 * 80 + ko);
#pragma unroll
            for (int j = 0; j < 4; j++) {
                uint32_t r[4];
                ldmatrix_x4(r, b_h + j * 16 * 80 + ko);
                bh[2 * j][0] = r[0]; bh[2 * j][1] = r[2];
                bh[2 * j + 1][0] = r[1]; bh[2 * j + 1][1] = r[3];
            }
#pragma unroll
            for (int i = 0; i < 2; i++)
#pragma unroll
                for (int n = 0; n < 8; n++)
                    mma16816(acc[i][n], ah[i], bh[n]);
            {
                uint32_t al[2][4];
                ldmatrix_x4(al[0], a_h + G_AL + ko);
                ldmatrix_x4(al[1], a_h + G_AL + 16 * 80 + ko);
#pragma unroll
                for (int i = 0; i < 2; i++)
#pragma unroll
                    for (int n = 0; n < 8; n++)
                        mma16816(acc[i][n], al[i], bh[n]);
            }
            {
                uint32_t bl[8][2];
#pragma unroll
                for (int j = 0; j < 4; j++) {
                    uint32_t r[4];
                    ldmatrix_x4(r, b_h + (G_BL - G_BH) + j * 16 * 80 + ko);
                    bl[2 * j][0] = r[0]; bl[2 * j][1] = r[2];
                    bl[2 * j + 1][0] = r[1]; bl[2 * j + 1][1] = r[3];
                }
#pragma unroll
                for (int i = 0; i < 2; i++)
#pragma unroll
                    for (int n = 0; n < 8; n++)
                        mma16816(acc[i][n], ah[i], bl[n]);
            }
        }
        __syncthreads();
    }
#undef GLOAD
}

// --------------------------- dual-problem GEMM -----------------------------
__global__ __launch_bounds__(256, 2)
void gemm_dual(const __nv_bfloat16* A1h, const __nv_bfloat16* A1l,
               const __nv_bfloat16* B1h, const __nv_bfloat16* B1l,
               float* C1, int M1, int N1,
               const __nv_bfloat16* A2h, const __nv_bfloat16* A2l,
               const __nv_bfloat16* B2h, const __nv_bfloat16* B2l,
               float* C2, int M2, int N2) {
    extern __shared__ __align__(16) char smd[];
    const int tid  = threadIdx.x;
    const int wid  = tid >> 5;
    const int lane = tid & 31;
    const uint32_t sb = smem_u32(smd);

    const __nv_bfloat16 *Ah_, *Al_, *Bh_, *Bl_;
    float* C;
    int M, Ntot, bm, bn;
    {
        const int nt1 = N1 >> 7, mt1 = (M1 + 127) >> 7;
        const int t1 = nt1 * mt1;
        int idx = blockIdx.x;
        if (idx < t1) {
            Ah_ = A1h; Al_ = A1l; Bh_ = B1h; Bl_ = B1l; C = C1; M = M1; Ntot = N1;
            bm = (idx / nt1) * 128; bn = (idx % nt1) * 128;
        } else {
            idx -= t1;
            const int nt2 = N2 >> 7;
            Ah_ = A2h; Al_ = A2l; Bh_ = B2h; Bl_ = B2l; C = C2; M = M2; Ntot = N2;
            bm = (idx / nt2) * 128; bn = (idx % nt2) * 128;
        }
    }

    float acc[2][8][4];
#pragma unroll
    for (int i = 0; i < 2; i++)
#pragma unroll
        for (int n = 0; n < 8; n++)
#pragma unroll
            for (int q = 0; q < 4; q++) acc[i][n][q] = 0.0f;

    mainloop128(Ah_, Al_, Bh_, Bl_, M, bm, bn, sb, tid, wid, lane, acc);

    const int wm = (wid >> 1) * 32;
    const int wn = (wid & 1) * 64;
#pragma unroll
    for (int i = 0; i < 2; i++) {
        const int ra = bm + wm + i * 16 + (lane >> 2);
        const int rb = ra + 8;
#pragma unroll
        for (int n = 0; n < 8; n++) {
            const int col = bn + wn + n * 8 + (lane & 3) * 2;
            if (ra < M)
                *(float2*)(C + (size_t)ra * Ntot + col) =
                    make_float2(acc[i][n][0], acc[i][n][1]);
            if (rb < M)
                *(float2*)(C + (size_t)rb * Ntot + col) =
                    make_float2(acc[i][n][2], acc[i][n][3]);
        }
    }
}

// --------------------------- internal x-GEMM -------------------------------
__global__ __launch_bounds__(256, 2)
void gemm_big(const __nv_bfloat16* __restrict__ Ah_, const __nv_bfloat16* __restrict__ Al_,
              const __nv_bfloat16* __restrict__ Bh_, const __nv_bfloat16* __restrict__ Bl_) {
    extern __shared__ __align__(16) char smd[];
    const int tid  = threadIdx.x;
    const int wid  = tid >> 5;
    const int lane = tid & 31;
    const int bm = blockIdx.y * 128;
    const int bn = blockIdx.x * 128;
    const int M = N_INT;
    const uint32_t sb = smem_u32(smd);

    float acc[2][8][4];
#pragma unroll
    for (int i = 0; i < 2; i++)
#pragma unroll
        for (int n = 0; n < 8; n++)
#pragma unroll
            for (int q = 0; q < 4; q++) acc[i][n][q] = 0.0f;

    mainloop128(Ah_, Al_, Bh_, Bl_, M, bm, bn, sb, tid, wid, lane, acc);

    // stage C tile, then coalesced float4 XW stores (+bias)
    float* Cs = (float*)smd;
    const int wm = (wid >> 1) * 32;
    const int wn = (wid & 1) * 64;
#pragma unroll
    for (int i = 0; i < 2; i++) {
        const int ral = wm + i * 16 + (lane >> 2);
#pragma unroll
        for (int n = 0; n < 8; n++) {
            const int col = wn + n * 8 + (lane & 3) * 2;
            *(float2*)(Cs + ral * SPITCH + col) = make_float2(acc[i][n][0], acc[i][n][1]);
            *(float2*)(Cs + (ral + 8) * SPITCH + col) = make_float2(acc[i][n][2], acc[i][n][3]);
        }
    }
    __syncthreads();

#pragma unroll 4
    for (int it = 0; it < 16; it++) {
        const int idx = it * 256 + tid;
        const int r = idx >> 5;
        const int t = idx & 31;
        const int row = bm + r;
        if (row >= M) continue;
        float4 v = *(float4*)(Cs + r * SPITCH + 4 * t);
        const float4 b = *(const float4*)(g_bcat + bn + 4 * t);
        v.x += b.x; v.y += b.y; v.z += b.z; v.w += b.w;
        *(float4*)(g_XW + (size_t)row * 1024 + bn + 4 * t) = v;
    }
}

// --------------------------- fused combine + parent hsum -------------------
__global__ void combine_fused(int node_off, int child_off) {
    __shared__ float hsm[4][256];
    const int s = threadIdx.x >> 8;
    const int j = threadIdx.x & 255;
    const int k = 4 * blockIdx.x + s;
    const size_t node = (size_t)node_off + k;

    const float4 xw = *(const float4*)(g_XW + node * 1024 + 4 * j);
    const float* iouh = &g_iouh[(size_t)k * 768 + 3 * j];

    float iv = fsig (xw.x + iouh[0]);
    float ov = fsig (xw.y + iouh[1]);
    float uv = ftanh(xw.z + iouh[2]);
    const float fx = xw.w;

    float acc = 0.0f;
#pragma unroll
    for (int b = 0; b < 4; b++) {
        size_t ch = (size_t)child_off + 4 * (size_t)k + b;
        float f = fsig(fx + g_fh[(4 * (size_t)k + b) * 256 + j]);
        acc = fmaf(f, g_c[ch * 256 + j], acc);
    }
    float c = fmaf(iv, uv, acc);
    float h = ov * ftanh(c);
    g_c[node * 256 + j] = c;
    split2(h, &g_h_hi[node * 256 + j], &g_h_lo[node * 256 + j]);

    hsm[s][j] = h;
    __syncthreads();
    if (s == 0) {
        float sum = hsm[0][j] + hsm[1][j] + hsm[2][j] + hsm[3][j];
        split2(sum, &g_hs_hi[blockIdx.x * 256 + j], &g_hs_lo[blockIdx.x * 256 + j]);
    }
}

__global__ void combine_root() {
    const int j = threadIdx.x;
    const float4 xw = *(const float4*)(g_XW + 4 * j);
    const float* iouh = &g_iouh[3 * j];
    float iv = fsig (xw.x + iouh[0]);
    float ov = fsig (xw.y + iouh[1]);
    float uv = ftanh(xw.z + iouh[2]);
    const float fx = xw.w;
    float acc = 0.0f;
#pragma unroll
    for (int b = 0; b < 4; b++) {
        float f = fsig(fx + g_fh[b * 256 + j]);
        acc = fmaf(f, g_c[(1 + b) * 256 + j], acc);
    }
    float c = fmaf(iv, uv, acc);
    float h = ov * ftanh(c);
    g_c[j] = c;
    g_hroot[j] = h;
}

__global__ void gather_hsum_leaf() {
    const int k = blockIdx.x;
    const int j = threadIdx.x;
    size_t base = ((size_t)LEAF_OFF + 4 * (size_t)k) * 256 + j;
    float s = 0.0f;
#pragma unroll
    for (int b = 0; b < 4; b++)
        s += __bfloat162float(g_h_hi[base + 256 * b]) + __bfloat162float(g_h_lo[base + 256 * b]);
    split2(s, &g_hs_hi[k * 256 + j], &g_hs_lo[k * 256 + j]);
}

__global__ void write_out(float* __restrict__ out) {
    int j = threadIdx.x;
    if (blockIdx.x == 0) out[j] = g_c[j];
    else                 out[256 + j] = g_hroot[j];
}

// --------------------------- launcher --------------------------------------
extern "C" void kernel_launch(void* const* d_in, const int* in_sizes, int n_in,
                              void* d_out, int out_size) {
    const float* x      = (const float*)d_in[0];
    const float* W_ioux = (const float*)d_in[1];
    const float* b_ioux = (const float*)d_in[2];
    const float* W_iouh = (const float*)d_in[3];
    const float* b_iouh = (const float*)d_in[4];
    const float* W_fx   = (const float*)d_in[5];
    const float* b_fx   = (const float*)d_in[6];
    const float* W_fh   = (const float*)d_in[7];
    const float* b_fh   = (const float*)d_in[8];

    cudaFuncSetAttribute(gemm_big,  cudaFuncAttributeMaxDynamicSharedMemorySize, BIG_SMEM);
    cudaFuncSetAttribute(gemm_dual, cudaFuncAttributeMaxDynamicSharedMemorySize, BIG_SMEM);
    cudaFuncSetAttribute(gemm_leaf, cudaFuncAttributeMaxDynamicSharedMemorySize, LEAF_SMEM);

    __nv_bfloat16 *xh, *xl, *hh, *hl, *hsh, *hsl;
    __nv_bfloat16 *wch, *wcl, *wlh, *wll, *wih, *wil, *wfh_, *wfl_;
    float *iouh, *fh;
    cudaGetSymbolAddress((void**)&xh,   g_x_hi);
    cudaGetSymbolAddress((void**)&xl,   g_x_lo);
    cudaGetSymbolAddress((void**)&hh,   g_h_hi);
    cudaGetSymbolAddress((void**)&hl,   g_h_lo);
    cudaGetSymbolAddress((void**)&hsh,  g_hs_hi);
    cudaGetSymbolAddress((void**)&hsl,  g_hs_lo);
    cudaGetSymbolAddress((void**)&wch,  g_Wcat_hi);
    cudaGetSymbolAddress((void**)&wcl,  g_Wcat_lo);
    cudaGetSymbolAddress((void**)&wlh,  g_Wiou_hi);
    cudaGetSymbolAddress((void**)&wll,  g_Wiou_lo);
    cudaGetSymbolAddress((void**)&wih,  g_Wiouh_hi);
    cudaGetSymbolAddress((void**)&wil,  g_Wiouh_lo);
    cudaGetSymbolAddress((void**)&wfh_, g_Wfh_hi);
    cudaGetSymbolAddress((void**)&wfl_, g_Wfh_lo);
    cudaGetSymbolAddress((void**)&iouh, g_iouh);
    cudaGetSymbolAddress((void**)&fh,   g_fh);

    // 1-3: pack / split
    split_x<<<N_NODES, 256>>>(x);
    pack_wcat<<<1024, 256>>>(W_ioux, b_ioux, b_iouh, W_fx, b_fx, b_fh);
    pack_rest<<<1792, 256>>>(W_ioux, b_ioux, b_iouh, W_iouh, W_fh);

    // 4: leaf GEMM + fused activation (PROFILED LAUNCH)
    {
        dim3 grid(8, N_LEAVES / 128);
        gemm_leaf<<<grid, 256, LEAF_SMEM>>>(&xh[(size_t)LEAF_OFF * 256],
                                            &xl[(size_t)LEAF_OFF * 256], wlh, wll);
    }

    // 5: internal x-GEMM -> XW
    {
        dim3 grid(8, (N_INT + 127) / 128);
        gemm_big<<<grid, 256, BIG_SMEM>>>(xh, xl, wch, wcl);
    }

    // 6: hsum for level 7
    gather_hsum_leaf<<<16384, 256>>>();

    // internal levels l = 7..0
    for (int l = 7; l >= 0; l--) {
        int n = 1 << (2 * l);
        int off = ((1 << (2 * l)) - 1) / 3;
        int choff = off + n;

        {   // fused dual GEMM: IOUH (n x 768) + FH (4n x 256)
            int mt1 = (n + 127) / 128;
            int mt2 = (4 * n + 127) / 128;
            int tiles = mt1 * 6 + mt2 * 2;
            gemm_dual<<<tiles, 256, BIG_SMEM>>>(
                hsh, hsl, wih, wil, iouh, n, 768,
                &hh[(size_t)choff * 256], &hl[(size_t)choff * 256], wfh_, wfl_,
                fh, 4 * n, 256);
        }
        if (l > 0) combine_fused<<<n / 4, 1024>>>(off, choff);
        else       combine_root<<<1, 256>>>();
    }

    write_out<<<2, 256>>>((float*)d_out);
}